// round 4
// baseline (speedup 1.0000x reference)
#include <cuda_runtime.h>
#include <math.h>
#include <stdint.h>

// NF4 quantize-dequantize, straight-through forward: out = data_type[idx]*s,
// s = per-row max|x| (clip 1e-6), idx = searchsorted(boundaries, x/s, left).
//
// R2: persistent double-buffered pipeline. 296 blocks x 512 threads; each block
// owns rows bid, bid+296, ... Row r+1's LDGs are issued before row r's
// compute+store, so DRAM reads and writes overlap chip-wide (R1 showed
// phase-separated waves capping DRAM at 41%).
//
// Exactness: per-row thresholds T_j = largest float with RN(t/s) <= b_j
// (nextafter-refined), so per-element (x/s > b_j) == (x > T_j) bit-exactly.
// 258-cell LUT over u = x*(128/s) + 129 via magic-FMA; min boundary gap
// (~0.085*s) >> cell width (s/128) => <=1 threshold per cell.

#define COLS  8192
#define NT    512
#define PERV  4            // float4 per thread (16 floats) per buffer
#define NB    15
#define NL    16
#define NCELL 258
#define GRID  296          // 2 blocks per SM x 148 SMs

__device__ __forceinline__ float absmax16(const float4* v) {
    float m = 0.0f;
#pragma unroll
    for (int i = 0; i < PERV; i++) {
        m = fmaxf(m, fabsf(v[i].x));
        m = fmaxf(m, fabsf(v[i].y));
        m = fmaxf(m, fabsf(v[i].z));
        m = fmaxf(m, fabsf(v[i].w));
    }
    return m;
}

__global__ __launch_bounds__(NT, 2)
void nf4_kernel(const float* __restrict__ x,
                const float* __restrict__ bnd,
                const float* __restrict__ dt,
                float* __restrict__ out,
                int rows)
{
    __shared__ float4 table[NCELL];   // {T, vlo, vhi, pad}
    __shared__ float Tsm[NB];
    __shared__ float Vsm[NL];
    __shared__ float wmax[NT / 32];
    __shared__ float c1S;

    const int tid = threadIdx.x;
    const int lane = tid & 31;

    int r = blockIdx.x;
    if (r >= rows) return;

    // ---- prologue: load first row ----
    float4 va[PERV];
    {
        const float4* rp = (const float4*)(x + (size_t)r * COLS);
#pragma unroll
        for (int i = 0; i < PERV; i++) va[i] = rp[tid + i * NT];
    }
    float mA = absmax16(va);

    while (true) {
        // ---- block reduce absmax -> scale; build per-row tables ----
        float m = mA;
#pragma unroll
        for (int o = 16; o; o >>= 1) m = fmaxf(m, __shfl_xor_sync(0xffffffffu, m, o));
        if (lane == 0) wmax[tid >> 5] = m;
        __syncthreads();   // also fences prior iteration's table reads

        float s;
        {
            float t = wmax[0];
#pragma unroll
            for (int i = 1; i < NT / 32; i++) t = fmaxf(t, wmax[i]);
            s = fmaxf(t, 1e-6f);
        }
        if (tid == 0) c1S = __fdiv_rn(128.0f, s);
        // exact raw-x thresholds: largest t with RN(t/s) <= boundary
        if (tid < NB) {
            const float mid = __ldg(bnd + tid);
            float t = mid * s;
            for (int it = 0; it < 8 && __fdiv_rn(t, s) <= mid; it++)
                t = nextafterf(t, __int_as_float(0x7f800000));
            for (int it = 0; it < 8 && __fdiv_rn(t, s) > mid; it++)
                t = nextafterf(t, __int_as_float(0xff800000));
            Tsm[tid] = t;
        }
        if (tid >= 32 && tid < 32 + NL)
            Vsm[tid - 32] = __ldg(dt + tid - 32) * s;   // RN, matches dt[idx]*s
        __syncthreads();

        // 258-cell LUT over u = x*c1 + 129
        {
            const float w = s * 0.0078125f;   // s/128
            const float padc = 0.05f * w;
            for (int k = tid; k < NCELL; k += NT) {
                const float L = ((float)k - 129.5f) * w - padc;
                const float R = ((float)k - 128.5f) * w + padc;
                int jb = 0;
#pragma unroll
                for (int jj = 0; jj < NB; jj++) jb += (Tsm[jj] < L) ? 1 : 0;
                float T = __int_as_float(0x7f800000);
                float vlo, vhi;
                if (jb < NB && Tsm[jb] <= R) {
                    T = Tsm[jb]; vlo = Vsm[jb]; vhi = Vsm[jb + 1];
                } else {
                    vlo = vhi = Vsm[jb];
                }
                table[k] = make_float4(T, vlo, vhi, 0.0f);
            }
        }
        __syncthreads();
        const float c1 = c1S;

        // ---- issue prefetch LDGs for next row (no consumer yet) ----
        const int rn = r + GRID;
        float4 vb[PERV];
        if (rn < rows) {
            const float4* rp = (const float4*)(x + (size_t)rn * COLS);
#pragma unroll
            for (int i = 0; i < PERV; i++) vb[i] = rp[tid + i * NT];
        }

        // ---- quantize current row from registers; store (overlaps prefetch) ----
        {
            float4* op = (float4*)(out + (size_t)r * COLS);
            const float MAGIC = 8388608.0f + 129.0f;   // 2^23 + 129
#pragma unroll
            for (int i = 0; i < PERV; i++) {
                const float4 a = va[i];
                float4 q;
                {
                    const int k = __float_as_int(fmaf(a.x, c1, MAGIC)) & 0x3ff;
                    const float4 e = table[k];
                    q.x = (a.x > e.x) ? e.z : e.y;
                }
                {
                    const int k = __float_as_int(fmaf(a.y, c1, MAGIC)) & 0x3ff;
                    const float4 e = table[k];
                    q.y = (a.y > e.x) ? e.z : e.y;
                }
                {
                    const int k = __float_as_int(fmaf(a.z, c1, MAGIC)) & 0x3ff;
                    const float4 e = table[k];
                    q.z = (a.z > e.x) ? e.z : e.y;
                }
                {
                    const int k = __float_as_int(fmaf(a.w, c1, MAGIC)) & 0x3ff;
                    const float4 e = table[k];
                    q.w = (a.w > e.x) ? e.z : e.y;
                }
                op[tid + i * NT] = q;
            }
        }

        if (rn >= rows) break;

        // consume prefetched row (scoreboard wait lands here, after stores issued)
        mA = absmax16(vb);
#pragma unroll
        for (int i = 0; i < PERV; i++) va[i] = vb[i];
        r = rn;
    }
}

extern "C" void kernel_launch(void* const* d_in, const int* in_sizes, int n_in,
                              void* d_out, int out_size)
{
    const float* x = nullptr;
    const float* bnd = nullptr;
    const float* dt = nullptr;
    long long nx = 0;
    for (int i = 0; i < n_in; i++) {
        if (in_sizes[i] == NB)      bnd = (const float*)d_in[i];
        else if (in_sizes[i] == NL) dt  = (const float*)d_in[i];
        else { x = (const float*)d_in[i]; nx = in_sizes[i]; }
    }
    const int rows = (int)(nx / COLS);
    const int grid = rows < GRID ? rows : GRID;
    nf4_kernel<<<grid, NT>>>(x, bnd, dt, (float*)d_out, rows);
}

// round 5
// speedup vs baseline: 1.1497x; 1.1497x over previous
#include <cuda_runtime.h>
#include <math.h>
#include <stdint.h>

// NF4 quantize-dequantize, straight-through forward: out = data_type[idx]*s,
// s = per-row max|x| (clip 1e-6), idx = searchsorted(boundaries, x/s, left).
//
// R5: concurrency restructure. 888 persistent blocks x 256 threads (5-6/SM).
// Each row is read twice: pass A streams it for absmax (no register storage),
// pass B re-reads it (L2 hit: ~28MB held << 126MB L2) while quantizing.
// Pass A of row r+GRID is interleaved with pass B of row r in the same loop
// body, so DRAM reads and writes co-occur even if blocks phase-lock.
//
// Exactness: thresholds T_j = largest float with RN(t/s) <= b_j (nextafter-
// refined) => (x/s > b_j) == (x > T_j) bit-exact. 258-cell LUT over
// u = x*(128/s)+129 via magic-FMA; cell width s/128 << min gap (~0.085*s).
// LUT split: Tarr[k] 4B + value pair Vint[2k + (x>T)] 4B.

#define COLS   8192
#define NF4    2048          // float4 per row
#define NT     256
#define CH     8             // float4 chunks per thread per row (2048/256)
#define NB     15
#define NL     16
#define NCELL  258
#define GRID   888           // ~6 blocks/SM target * 148 SMs

__global__ __launch_bounds__(NT, 5)
void nf4_kernel(const float* __restrict__ x,
                const float* __restrict__ bnd,
                const float* __restrict__ dt,
                float* __restrict__ out,
                int rows)
{
    __shared__ float Tarr[NCELL];
    __shared__ float Vint[2 * NCELL];
    __shared__ float Tsm[NB];
    __shared__ float Vsm[NL];
    __shared__ float wmax[NT / 32];

    const int tid = threadIdx.x;
    const int lane = tid & 31;
    const float4* __restrict__ xv = (const float4*)x;
    float4* __restrict__ ov = (float4*)out;
    const float MAGIC = 8388608.0f + 129.0f;   // 2^23 + 129

    int r = blockIdx.x;
    if (r >= rows) return;

    // ---- pass A, first row: streaming absmax (no storage) ----
    float m = 0.0f;
    {
        const float4* rp = xv + (size_t)r * NF4;
#pragma unroll
        for (int i = 0; i < CH; i++) {
            const float4 a = rp[tid + i * NT];
            m = fmaxf(m, fmaxf(fmaxf(fabsf(a.x), fabsf(a.y)),
                               fmaxf(fabsf(a.z), fabsf(a.w))));
        }
    }

    while (true) {
        // ---- block reduce -> s (redundant per-thread, avoids broadcast sync) ----
#pragma unroll
        for (int o = 16; o; o >>= 1) m = fmaxf(m, __shfl_xor_sync(0xffffffffu, m, o));
        __syncthreads();                 // prior iter's table/wmax readers done
        if (lane == 0) wmax[tid >> 5] = m;
        __syncthreads();
        float s = wmax[0];
#pragma unroll
        for (int i = 1; i < NT / 32; i++) s = fmaxf(s, wmax[i]);
        s = fmaxf(s, 1e-6f);             // jnp.clip(..., 1e-6)
        const float c1 = __fdiv_rn(128.0f, s);

        // exact raw-x thresholds + scaled levels
        if (tid < NB) {
            const float mid = __ldg(bnd + tid);
            float t = mid * s;
            for (int it = 0; it < 8 && __fdiv_rn(t, s) <= mid; it++)
                t = nextafterf(t, __int_as_float(0x7f800000));
            for (int it = 0; it < 8 && __fdiv_rn(t, s) > mid; it++)
                t = nextafterf(t, __int_as_float(0xff800000));
            Tsm[tid] = t;
        }
        if (tid >= 32 && tid < 32 + NL)
            Vsm[tid - 32] = __ldg(dt + tid - 32) * s;   // RN, matches dt[idx]*s
        __syncthreads();

        // ---- build LUT: Tarr + interleaved value pairs ----
        {
            const float w = s * 0.0078125f;   // s/128
            const float padc = 0.05f * w;
            for (int k = tid; k < NCELL; k += NT) {
                const float L = ((float)k - 129.5f) * w - padc;
                const float R = ((float)k - 128.5f) * w + padc;
                int jb = 0;
#pragma unroll
                for (int jj = 0; jj < NB; jj++) jb += (Tsm[jj] < L) ? 1 : 0;
                float T = __int_as_float(0x7f800000);
                float vlo, vhi;
                if (jb < NB && Tsm[jb] <= R) {
                    T = Tsm[jb]; vlo = Vsm[jb]; vhi = Vsm[jb + 1];
                } else {
                    vlo = vhi = Vsm[jb];
                }
                Tarr[k] = T;
                Vint[2 * k]     = vlo;
                Vint[2 * k + 1] = vhi;
            }
        }
        __syncthreads();

        const int rn = r + GRID;
        const float4* rpB = xv + (size_t)r * NF4;   // L2/L1 hit (read in pass A)
        float4* wp = ov + (size_t)r * NF4;

        if (rn < rows) {
            // ---- interleaved: pass A of row rn (DRAM read) + pass B of row r ----
            const float4* rpA = xv + (size_t)rn * NF4;
            float mn = 0.0f;
#pragma unroll
            for (int i = 0; i < CH; i++) {
                const float4 a = rpA[tid + i * NT];    // DRAM read, next row
                const float4 b = rpB[tid + i * NT];    // L2 hit, current row
                mn = fmaxf(mn, fmaxf(fmaxf(fabsf(a.x), fabsf(a.y)),
                                     fmaxf(fabsf(a.z), fabsf(a.w))));
                float4 q;
                {
                    const int k = __float_as_int(fmaf(b.x, c1, MAGIC)) & 0x3ff;
                    q.x = Vint[2 * k + ((b.x > Tarr[k]) ? 1 : 0)];
                }
                {
                    const int k = __float_as_int(fmaf(b.y, c1, MAGIC)) & 0x3ff;
                    q.y = Vint[2 * k + ((b.y > Tarr[k]) ? 1 : 0)];
                }
                {
                    const int k = __float_as_int(fmaf(b.z, c1, MAGIC)) & 0x3ff;
                    q.z = Vint[2 * k + ((b.z > Tarr[k]) ? 1 : 0)];
                }
                {
                    const int k = __float_as_int(fmaf(b.w, c1, MAGIC)) & 0x3ff;
                    q.w = Vint[2 * k + ((b.w > Tarr[k]) ? 1 : 0)];
                }
                wp[tid + i * NT] = q;                  // DRAM write
            }
            m = mn;
            r = rn;
        } else {
            // ---- final row: pass B only ----
#pragma unroll
            for (int i = 0; i < CH; i++) {
                const float4 b = rpB[tid + i * NT];
                float4 q;
                {
                    const int k = __float_as_int(fmaf(b.x, c1, MAGIC)) & 0x3ff;
                    q.x = Vint[2 * k + ((b.x > Tarr[k]) ? 1 : 0)];
                }
                {
                    const int k = __float_as_int(fmaf(b.y, c1, MAGIC)) & 0x3ff;
                    q.y = Vint[2 * k + ((b.y > Tarr[k]) ? 1 : 0)];
                }
                {
                    const int k = __float_as_int(fmaf(b.z, c1, MAGIC)) & 0x3ff;
                    q.z = Vint[2 * k + ((b.z > Tarr[k]) ? 1 : 0)];
                }
                {
                    const int k = __float_as_int(fmaf(b.w, c1, MAGIC)) & 0x3ff;
                    q.w = Vint[2 * k + ((b.w > Tarr[k]) ? 1 : 0)];
                }
                wp[tid + i * NT] = q;
            }
            break;
        }
    }
}

extern "C" void kernel_launch(void* const* d_in, const int* in_sizes, int n_in,
                              void* d_out, int out_size)
{
    const float* x = nullptr;
    const float* bnd = nullptr;
    const float* dt = nullptr;
    long long nx = 0;
    for (int i = 0; i < n_in; i++) {
        if (in_sizes[i] == NB)      bnd = (const float*)d_in[i];
        else if (in_sizes[i] == NL) dt  = (const float*)d_in[i];
        else { x = (const float*)d_in[i]; nx = in_sizes[i]; }
    }
    const int rows = (int)(nx / COLS);
    const int grid = rows < GRID ? rows : GRID;
    nf4_kernel<<<grid, NT>>>(x, bnd, dt, (float*)d_out, rows);
}